// round 4
// baseline (speedup 1.0000x reference)
#include <cuda_runtime.h>
#include <cuda_bf16.h>
#include <cstdint>
#include <math.h>

#define L_SEQ 4096
#define H_DIM 1024
#define E_DIM 1024
#define H3    3072
#define T_DIM 512

#define RNN_NCTA 128
#define NIDX 8                    // outputs per CTA per direction
#define RNN_THREADS 256

typedef unsigned long long ull;

// ---------------- device scratch (no allocations allowed) ----------------
__device__ float g_gx[4][L_SEQ][H3];          // [sent*2+dir][t][3H]
__device__ float g_h[2][2][2][H_DIM];         // [buf][dir][sent][H]
__device__ float g_hs[4];
__device__ unsigned int g_flag[2][RNN_NCTA * 32];   // [dir][cta], 128B padded

// ---------------- helpers ----------------
__device__ __forceinline__ unsigned tf32_of(float f) {
  unsigned r; asm("cvt.rna.tf32.f32 %0, %1;" : "=r"(r) : "f"(f)); return r;
}
__device__ __forceinline__ void mma_tf32(float* c, const unsigned* a, const unsigned* b) {
  asm volatile("mma.sync.aligned.m16n8k8.row.col.f32.tf32.tf32.f32 "
    "{%0,%1,%2,%3},{%4,%5,%6,%7},{%8,%9},{%0,%1,%2,%3};"
    : "+f"(c[0]), "+f"(c[1]), "+f"(c[2]), "+f"(c[3])
    : "r"(a[0]), "r"(a[1]), "r"(a[2]), "r"(a[3]), "r"(b[0]), "r"(b[1]));
}
__device__ __forceinline__ float sigm(float x) { return 1.f / (1.f + __expf(-x)); }

__device__ __forceinline__ void ffma2(ull& d, ull a, ull b) {
  asm("fma.rn.f32x2 %0, %1, %2, %0;" : "+l"(d) : "l"(a), "l"(b));
}
__device__ __forceinline__ float pairsum(ull v) {
  float x, y;
  asm("mov.b64 {%0,%1}, %2;" : "=f"(x), "=f"(y) : "l"(v));
  return x + y;
}
__device__ __forceinline__ void ldcg_v2u64(const void* p, ull& x, ull& y) {
  asm volatile("ld.global.cg.v2.u64 {%0,%1}, [%2];" : "=l"(x), "=l"(y) : "l"(p));
}
__device__ __forceinline__ unsigned ld_acq(const unsigned* p) {
  unsigned v;
  asm volatile("ld.acquire.gpu.u32 %0, [%1];" : "=r"(v) : "l"(p) : "memory");
  return v;
}
__device__ __forceinline__ void st_rel(unsigned* p, unsigned v) {
  asm volatile("st.release.gpu.u32 [%0], %1;" :: "l"(p), "r"(v) : "memory");
}

// ---------------- init ----------------
__global__ void init_kernel(const float* __restrict__ hidden) {
  int i = blockIdx.x * blockDim.x + threadIdx.x;
  if (i < 2 * RNN_NCTA * 32) ((unsigned*)g_flag)[i] = 0u;
  if (i < 4) g_hs[i] = 0.f;
  if (i < 2 * H_DIM) {
    int d = i / H_DIM, j = i % H_DIM;
    g_h[0][d][0][j] = hidden[i];
    g_h[0][d][1][j] = hidden[i];
  }
}

// ---------------- gx GEMM ----------------
__global__ __launch_bounds__(256) void gemm_gx(
    const int* __restrict__ sA, const int* __restrict__ sB,
    const float* __restrict__ emb,
    const float* __restrict__ wf, const float* __restrict__ wr,
    const float* __restrict__ bihf, const float* __restrict__ bhhf,
    const float* __restrict__ bihr, const float* __restrict__ bhhr) {
  __shared__ float As[128][17];
  __shared__ float Bs[128][17];

  int z = blockIdx.z;
  const int*   toks = (z >> 1) ? sB : sA;
  const float* W    = (z & 1) ? wr   : wf;
  const float* bih  = (z & 1) ? bihr : bihf;
  const float* bhh  = (z & 1) ? bhhr : bhhf;

  int m0 = blockIdx.y * 128, n0 = blockIdx.x * 128;
  int tid = threadIdx.x, lane = tid & 31, warp = tid >> 5;
  int wm = warp & 3, wn = warp >> 2;
  int gid = lane >> 2, tig = lane & 3;

  int ar = tid >> 1, ac = (tid & 1) * 8;
  const float* aSrc = emb + (size_t)toks[m0 + ar] * E_DIM + ac;
  const float* bSrc = W   + (size_t)(n0 + ar) * E_DIM + ac;

  float c[2][8][4];
  #pragma unroll
  for (int mi = 0; mi < 2; mi++)
    #pragma unroll
    for (int ni = 0; ni < 8; ni++)
      #pragma unroll
      for (int q = 0; q < 4; q++) c[mi][ni][q] = 0.f;

  for (int k0 = 0; k0 < E_DIM; k0 += 16) {
    float4 av0 = *(const float4*)(aSrc + k0);
    float4 av1 = *(const float4*)(aSrc + k0 + 4);
    float4 bv0 = *(const float4*)(bSrc + k0);
    float4 bv1 = *(const float4*)(bSrc + k0 + 4);
    __syncthreads();
    As[ar][ac+0]=av0.x; As[ar][ac+1]=av0.y; As[ar][ac+2]=av0.z; As[ar][ac+3]=av0.w;
    As[ar][ac+4]=av1.x; As[ar][ac+5]=av1.y; As[ar][ac+6]=av1.z; As[ar][ac+7]=av1.w;
    Bs[ar][ac+0]=bv0.x; Bs[ar][ac+1]=bv0.y; Bs[ar][ac+2]=bv0.z; Bs[ar][ac+3]=bv0.w;
    Bs[ar][ac+4]=bv1.x; Bs[ar][ac+5]=bv1.y; Bs[ar][ac+6]=bv1.z; Bs[ar][ac+7]=bv1.w;
    __syncthreads();

    #pragma unroll
    for (int kk = 0; kk < 16; kk += 8) {
      unsigned a[2][4];
      #pragma unroll
      for (int mi = 0; mi < 2; mi++) {
        int r0 = wm * 32 + mi * 16 + gid;
        a[mi][0] = tf32_of(As[r0    ][kk + tig    ]);
        a[mi][1] = tf32_of(As[r0 + 8][kk + tig    ]);
        a[mi][2] = tf32_of(As[r0    ][kk + tig + 4]);
        a[mi][3] = tf32_of(As[r0 + 8][kk + tig + 4]);
      }
      unsigned b[8][2];
      #pragma unroll
      for (int ni = 0; ni < 8; ni++) {
        int cc = wn * 64 + ni * 8 + gid;
        b[ni][0] = tf32_of(Bs[cc][kk + tig    ]);
        b[ni][1] = tf32_of(Bs[cc][kk + tig + 4]);
      }
      #pragma unroll
      for (int mi = 0; mi < 2; mi++)
        #pragma unroll
        for (int ni = 0; ni < 8; ni++)
          mma_tf32(c[mi][ni], a[mi], b[ni]);
    }
  }

  #pragma unroll
  for (int mi = 0; mi < 2; mi++) {
    int row = m0 + wm * 32 + mi * 16 + gid;
    #pragma unroll
    for (int ni = 0; ni < 8; ni++) {
      int colb = n0 + wn * 64 + ni * 8 + 2 * tig;
      float bb0 = bih[colb]     + (colb     < 2 * H_DIM ? bhh[colb]     : 0.f);
      float bb1 = bih[colb + 1] + (colb + 1 < 2 * H_DIM ? bhh[colb + 1] : 0.f);
      float2 v0 = make_float2(c[mi][ni][0] + bb0, c[mi][ni][1] + bb1);
      float2 v1 = make_float2(c[mi][ni][2] + bb0, c[mi][ni][3] + bb1);
      *(float2*)&g_gx[z][row    ][colb] = v0;
      *(float2*)&g_gx[z][row + 8][colb] = v1;
    }
  }
}

// ---------------- persistent GRU recurrence, direction-interleaved ----------------
// 128 CTAs, each owns NIDX=8 output indices of BOTH directions (24+24 w_hh rows
// in SMEM). Per step: [phase d0: wait d0 flags -> load h0 -> dots -> bar ->
// warp0 gates+release] then same for d1. Each wait's latency is hidden behind
// the other direction's compute phase.
extern __shared__ float s_dyn[];

__global__ __launch_bounds__(RNN_THREADS, 1) void rnn_kernel(
    const float* __restrict__ whf, const float* __restrict__ whr,
    const float* __restrict__ bhhf, const float* __restrict__ bhhr) {
  float* sW  = s_dyn;                        // 48 * H_DIM
  float* sGh = sW + 48 * H_DIM;              // [d][s][24] = 96

  int cta = blockIdx.x;
  int i0  = cta * NIDX;
  int tid = threadIdx.x, lane = tid & 31, warp = tid >> 5;

  // stage 24 fwd + 24 rev w_hh rows into SMEM (once)
  for (int r = 0; r < 48; r++) {
    int dd = r / 24, loc = r % 24, g = loc >> 3, li = loc & 7;
    const float* src = (dd ? whr : whf) + (size_t)(g * H_DIM + i0 + li) * H_DIM;
    for (int k = tid; k < H_DIM; k += RNN_THREADS) sW[r * H_DIM + k] = src[k];
  }

  bool isGate = tid < 16;                    // (sentence, idx) pairs
  int gs = tid & 1, gli = tid >> 1;
  float bhn[2] = {0.f, 0.f}, hold[2] = {0.f, 0.f};
  float gxc[2][3];
  if (isGate) {
    bhn[0]  = bhhf[2 * H_DIM + i0 + gli];
    bhn[1]  = bhhr[2 * H_DIM + i0 + gli];
    hold[0] = g_h[0][0][gs][i0 + gli];
    hold[1] = g_h[0][1][gs][i0 + gli];
    #pragma unroll
    for (int dd = 0; dd < 2; dd++) {
      int trow = dd ? (L_SEQ - 1) : 0;
      const float* gxp = &g_gx[gs * 2 + dd][trow][0];
      gxc[dd][0] = __ldg(gxp + i0 + gli);
      gxc[dd][1] = __ldg(gxp + H_DIM + i0 + gli);
      gxc[dd][2] = __ldg(gxp + 2 * H_DIM + i0 + gli);
    }
  }
  __syncthreads();

  ull hA01[8], hA23[8], hB01[8], hB23[8];
  float gxn_[2][3];

  for (int t = 0; t < L_SEQ; t++) {
    int cur = t & 1, nxt = cur ^ 1;

    // prefetch gx for step t+1 (independent of flags; hides DRAM latency)
    if (isGate) {
      int tp = (t + 1 < L_SEQ) ? t + 1 : t;
      #pragma unroll
      for (int dd = 0; dd < 2; dd++) {
        int trow = dd ? (L_SEQ - 1 - tp) : tp;
        const float* gxp = &g_gx[gs * 2 + dd][trow][0];
        gxn_[dd][0] = __ldg(gxp + i0 + gli);
        gxn_[dd][1] = __ldg(gxp + H_DIM + i0 + gli);
        gxn_[dd][2] = __ldg(gxp + 2 * H_DIM + i0 + gli);
      }
    }

    #pragma unroll
    for (int d = 0; d < 2; d++) {
      // wait until all 128 CTAs published h_d(t)  (hidden behind other phase)
      if (t) {
        const unsigned* fl = &g_flag[d][0];
        unsigned tgt = (unsigned)t;
        for (;;) {
          unsigned a = ld_acq(fl + lane * 32);
          unsigned b = ld_acq(fl + (lane + 32) * 32);
          unsigned c = ld_acq(fl + (lane + 64) * 32);
          unsigned e = ld_acq(fl + (lane + 96) * 32);
          unsigned m = min(min(a, b), min(c, e));
          if (__all_sync(0xffffffffu, m >= tgt)) break;
        }
      }

      // load h_d(t), packed f32x2 (L2-coherent .cg)
      {
        const char* pA = (const char*)&g_h[cur][d][0][0];
        const char* pB = (const char*)&g_h[cur][d][1][0];
        #pragma unroll
        for (int j = 0; j < 8; j++) {
          int off = (j * 128 + lane * 4) * 4;
          ldcg_v2u64(pA + off, hA01[j], hA23[j]);
          ldcg_v2u64(pB + off, hB01[j], hB23[j]);
        }
      }

      // 3 rows per warp x 2 sentences
      #pragma unroll
      for (int g = 0; g < 3; g++) {
        const float* wrow = sW + (d * 24 + g * 8 + warp) * H_DIM + lane * 4;
        ull aA0 = 0, aA1 = 0, aB0 = 0, aB1 = 0;
        #pragma unroll
        for (int j = 0; j < 8; j++) {
          ulonglong2 w = *(const ulonglong2*)(wrow + j * 128);
          ffma2(aA0, w.x, hA01[j]);
          ffma2(aA1, w.y, hA23[j]);
          ffma2(aB0, w.x, hB01[j]);
          ffma2(aB1, w.y, hB23[j]);
        }
        float va = pairsum(aA0) + pairsum(aA1);
        float vb = pairsum(aB0) + pairsum(aB1);
        #pragma unroll
        for (int off = 16; off > 0; off >>= 1) {
          va += __shfl_xor_sync(0xffffffffu, va, off);
          vb += __shfl_xor_sync(0xffffffffu, vb, off);
        }
        if (lane == 0) {
          sGh[d * 48          + g * 8 + warp] = va;
          sGh[d * 48 + 24     + g * 8 + warp] = vb;
        }
      }
      __syncthreads();     // sGh[d] ready

      // warp 0: gates + publish (other warps proceed to next phase)
      if (warp == 0) {
        if (isGate) {
          float ghr = sGh[d * 48 + gs * 24 + gli];
          float ghz = sGh[d * 48 + gs * 24 + 8 + gli];
          float ghn = sGh[d * 48 + gs * 24 + 16 + gli];
          float r_ = sigm(gxc[d][0] + ghr);
          float z_ = sigm(gxc[d][1] + ghz);
          float ag = gxc[d][2] + r_ * (ghn + bhn[d]);
          ag = fminf(fmaxf(ag, -15.f), 15.f);
          float e = __expf(-2.f * ag);
          float n_ = (1.f - e) / (1.f + e);
          float hnew = (1.f - z_) * n_ + z_ * hold[d];
          hold[d] = hnew;
          g_h[nxt][d][gs][i0 + gli] = hnew;
        }
        __syncwarp();
        if (lane == 0) st_rel(&g_flag[d][cta * 32], (unsigned)(t + 1));
      }
    }

    if (isGate) {
      #pragma unroll
      for (int dd = 0; dd < 2; dd++)
        #pragma unroll
        for (int q = 0; q < 3; q++) gxc[dd][q] = gxn_[dd][q];
    }
  }
}

// ---------------- head ----------------
__global__ __launch_bounds__(256) void head1(const float* __restrict__ W2,
                                             const float* __restrict__ b2) {
  __shared__ float ht[H_DIM];
  __shared__ float wsum[8];
  int j = blockIdx.x, tid = threadIdx.x, lane = tid & 31, warp = tid >> 5;
  const float* fA = (j < 2) ? &g_h[0][0][0][0] : &g_h[0][1][0][0];
  const float* fB = (j < 2) ? &g_h[0][0][1][0] : &g_h[0][1][1][0];
  for (int k = tid; k < H_DIM; k += 256) {
    float a = fA[k], b = fB[k];
    ht[k] = (j & 1) ? a * b : fabsf(a - b);
  }
  __syncthreads();

  int tbase = blockIdx.y * 64;
  float acc = 0.f;
  for (int t = tbase + warp; t < tbase + 64; t += 8) {
    const float4* w = (const float4*)(W2 + (size_t)t * H_DIM) + lane;
    const float4* h4 = (const float4*)ht + lane;
    float dsum = 0.f;
    #pragma unroll
    for (int q = 0; q < 8; q++) {
      float4 wv = __ldg(w + q * 32);
      float4 hv = h4[q * 32];
      dsum += wv.x * hv.x + wv.y * hv.y + wv.z * hv.z + wv.w * hv.w;
    }
    #pragma unroll
    for (int off = 16; off > 0; off >>= 1)
      dsum += __shfl_xor_sync(0xffffffffu, dsum, off);
    if (lane == 0) acc += fmaxf(dsum + b2[t], 0.f);
  }
  if (lane == 0) wsum[warp] = acc;
  __syncthreads();
  if (tid == 0) {
    float s = 0.f;
    #pragma unroll
    for (int w = 0; w < 8; w++) s += wsum[w];
    atomicAdd(&g_hs[j], s);
  }
}

__global__ void head2(const float* __restrict__ Wl, const float* __restrict__ bl,
                      float* __restrict__ out) {
  float s = bl[0];
  #pragma unroll
  for (int j = 0; j < 4; j++) s += g_hs[j] * Wl[j];
  out[0] = 1.f / (1.f + __expf(-s));
}

// ---------------- launch ----------------
extern "C" void kernel_launch(void* const* d_in, const int* in_sizes, int n_in,
                              void* d_out, int out_size) {
  const int*   sentA  = (const int*)d_in[0];
  const int*   sentB  = (const int*)d_in[1];
  const float* hidden = (const float*)d_in[2];
  const float* emb    = (const float*)d_in[3];
  const float* w_ih_f = (const float*)d_in[4];
  const float* w_hh_f = (const float*)d_in[5];
  const float* b_ih_f = (const float*)d_in[6];
  const float* b_hh_f = (const float*)d_in[7];
  const float* w_ih_r = (const float*)d_in[8];
  const float* w_hh_r = (const float*)d_in[9];
  const float* b_ih_r = (const float*)d_in[10];
  const float* b_hh_r = (const float*)d_in[11];
  const float* W2     = (const float*)d_in[12];
  const float* b2     = (const float*)d_in[13];
  const float* Wl     = (const float*)d_in[14];
  const float* bl     = (const float*)d_in[15];
  float* out = (float*)d_out;

  int rnn_smem = (48 * H_DIM + 96) * (int)sizeof(float);
  cudaFuncSetAttribute(rnn_kernel, cudaFuncAttributeMaxDynamicSharedMemorySize, rnn_smem);

  init_kernel<<<32, 256>>>(hidden);

  dim3 ggrid(H3 / 128, L_SEQ / 128, 4);
  gemm_gx<<<ggrid, 256>>>(sentA, sentB, emb, w_ih_f, w_ih_r,
                          b_ih_f, b_hh_f, b_ih_r, b_hh_r);

  rnn_kernel<<<RNN_NCTA, RNN_THREADS, rnn_smem>>>(w_hh_f, w_hh_r, b_hh_f, b_hh_r);

  head1<<<dim3(4, 8), 256>>>(W2, b2);
  head2<<<1, 1>>>(Wl, bl, out);
}

// round 5
// speedup vs baseline: 1.5554x; 1.5554x over previous
#include <cuda_runtime.h>
#include <cuda_bf16.h>
#include <cstdint>
#include <math.h>

#define L_SEQ 4096
#define H_DIM 1024
#define E_DIM 1024
#define H3    3072
#define T_DIM 512

#define RNN_NCTA 128
#define NIDX 16
#define RNN_THREADS 256

typedef unsigned long long ull;

// ---------------- device scratch ----------------
__device__ float g_gx[4][L_SEQ][H3];          // [sent*2+dir][t][3H]
__device__ float g_h[2][2][2][H_DIM];         // [buf][dir][sent][H]
__device__ float g_hs[4];
__device__ unsigned int g_flag[RNN_NCTA * 32];   // per-CTA, 128B padded

// ---------------- helpers ----------------
__device__ __forceinline__ unsigned tf32_of(float f) {
  unsigned r; asm("cvt.rna.tf32.f32 %0, %1;" : "=r"(r) : "f"(f)); return r;
}
__device__ __forceinline__ void mma_tf32(float* c, const unsigned* a, const unsigned* b) {
  asm volatile("mma.sync.aligned.m16n8k8.row.col.f32.tf32.tf32.f32 "
    "{%0,%1,%2,%3},{%4,%5,%6,%7},{%8,%9},{%0,%1,%2,%3};"
    : "+f"(c[0]), "+f"(c[1]), "+f"(c[2]), "+f"(c[3])
    : "r"(a[0]), "r"(a[1]), "r"(a[2]), "r"(a[3]), "r"(b[0]), "r"(b[1]));
}
__device__ __forceinline__ float sigm(float x) { return 1.f / (1.f + __expf(-x)); }

__device__ __forceinline__ void ffma2(ull& d, ull a, ull b) {
  asm("fma.rn.f32x2 %0, %1, %2, %0;" : "+l"(d) : "l"(a), "l"(b));
}
__device__ __forceinline__ float pairsum(ull v) {
  float x, y;
  asm("mov.b64 {%0,%1}, %2;" : "=f"(x), "=f"(y) : "l"(v));
  return x + y;
}
__device__ __forceinline__ unsigned ld_acq(const unsigned* p) {
  unsigned v;
  asm volatile("ld.acquire.gpu.u32 %0, [%1];" : "=r"(v) : "l"(p) : "memory");
  return v;
}
__device__ __forceinline__ void st_rel(unsigned* p, unsigned v) {
  asm volatile("st.release.gpu.u32 [%0], %1;" :: "l"(p), "r"(v) : "memory");
}
__device__ __forceinline__ float4 ldcg_f4(const float4* p) {
  float4 v;
  asm volatile("ld.global.cg.v4.f32 {%0,%1,%2,%3}, [%4];"
    : "=f"(v.x), "=f"(v.y), "=f"(v.z), "=f"(v.w) : "l"(p));
  return v;
}

// ---------------- init ----------------
__global__ void init_kernel(const float* __restrict__ hidden) {
  int i = blockIdx.x * blockDim.x + threadIdx.x;
  if (i < RNN_NCTA * 32) g_flag[i] = 0u;
  if (i < 4) g_hs[i] = 0.f;
  if (i < 2 * H_DIM) {
    int d = i / H_DIM, j = i % H_DIM;
    g_h[0][d][0][j] = hidden[i];
    g_h[0][d][1][j] = hidden[i];
  }
}

// ---------------- gx GEMM ----------------
__global__ __launch_bounds__(256) void gemm_gx(
    const int* __restrict__ sA, const int* __restrict__ sB,
    const float* __restrict__ emb,
    const float* __restrict__ wf, const float* __restrict__ wr,
    const float* __restrict__ bihf, const float* __restrict__ bhhf,
    const float* __restrict__ bihr, const float* __restrict__ bhhr) {
  __shared__ float As[128][17];
  __shared__ float Bs[128][17];

  int z = blockIdx.z;
  const int*   toks = (z >> 1) ? sB : sA;
  const float* W    = (z & 1) ? wr   : wf;
  const float* bih  = (z & 1) ? bihr : bihf;
  const float* bhh  = (z & 1) ? bhhr : bhhf;

  int m0 = blockIdx.y * 128, n0 = blockIdx.x * 128;
  int tid = threadIdx.x, lane = tid & 31, warp = tid >> 5;
  int wm = warp & 3, wn = warp >> 2;
  int gid = lane >> 2, tig = lane & 3;

  int ar = tid >> 1, ac = (tid & 1) * 8;
  const float* aSrc = emb + (size_t)toks[m0 + ar] * E_DIM + ac;
  const float* bSrc = W   + (size_t)(n0 + ar) * E_DIM + ac;

  float c[2][8][4];
  #pragma unroll
  for (int mi = 0; mi < 2; mi++)
    #pragma unroll
    for (int ni = 0; ni < 8; ni++)
      #pragma unroll
      for (int q = 0; q < 4; q++) c[mi][ni][q] = 0.f;

  for (int k0 = 0; k0 < E_DIM; k0 += 16) {
    float4 av0 = *(const float4*)(aSrc + k0);
    float4 av1 = *(const float4*)(aSrc + k0 + 4);
    float4 bv0 = *(const float4*)(bSrc + k0);
    float4 bv1 = *(const float4*)(bSrc + k0 + 4);
    __syncthreads();
    As[ar][ac+0]=av0.x; As[ar][ac+1]=av0.y; As[ar][ac+2]=av0.z; As[ar][ac+3]=av0.w;
    As[ar][ac+4]=av1.x; As[ar][ac+5]=av1.y; As[ar][ac+6]=av1.z; As[ar][ac+7]=av1.w;
    Bs[ar][ac+0]=bv0.x; Bs[ar][ac+1]=bv0.y; Bs[ar][ac+2]=bv0.z; Bs[ar][ac+3]=bv0.w;
    Bs[ar][ac+4]=bv1.x; Bs[ar][ac+5]=bv1.y; Bs[ar][ac+6]=bv1.z; Bs[ar][ac+7]=bv1.w;
    __syncthreads();

    #pragma unroll
    for (int kk = 0; kk < 16; kk += 8) {
      unsigned a[2][4];
      #pragma unroll
      for (int mi = 0; mi < 2; mi++) {
        int r0 = wm * 32 + mi * 16 + gid;
        a[mi][0] = tf32_of(As[r0    ][kk + tig    ]);
        a[mi][1] = tf32_of(As[r0 + 8][kk + tig    ]);
        a[mi][2] = tf32_of(As[r0    ][kk + tig + 4]);
        a[mi][3] = tf32_of(As[r0 + 8][kk + tig + 4]);
      }
      unsigned b[8][2];
      #pragma unroll
      for (int ni = 0; ni < 8; ni++) {
        int cc = wn * 64 + ni * 8 + gid;
        b[ni][0] = tf32_of(Bs[cc][kk + tig    ]);
        b[ni][1] = tf32_of(Bs[cc][kk + tig + 4]);
      }
      #pragma unroll
      for (int mi = 0; mi < 2; mi++)
        #pragma unroll
        for (int ni = 0; ni < 8; ni++)
          mma_tf32(c[mi][ni], a[mi], b[ni]);
    }
  }

  #pragma unroll
  for (int mi = 0; mi < 2; mi++) {
    int row = m0 + wm * 32 + mi * 16 + gid;
    #pragma unroll
    for (int ni = 0; ni < 8; ni++) {
      int colb = n0 + wn * 64 + ni * 8 + 2 * tig;
      float bb0 = bih[colb]     + (colb     < 2 * H_DIM ? bhh[colb]     : 0.f);
      float bb1 = bih[colb + 1] + (colb + 1 < 2 * H_DIM ? bhh[colb + 1] : 0.f);
      float2 v0 = make_float2(c[mi][ni][0] + bb0, c[mi][ni][1] + bb1);
      float2 v1 = make_float2(c[mi][ni][2] + bb0, c[mi][ni][3] + bb1);
      *(float2*)&g_gx[z][row    ][colb] = v0;
      *(float2*)&g_gx[z][row + 8][colb] = v1;
    }
  }
}

// ---------------- persistent GRU recurrence ----------------
// 128 CTAs: d = cta/64, outputs [i0, i0+16). w_hh k-chunks 0..3 in REGISTERS
// (96 regs/thread), chunks 4..7 in SMEM. h staged via SMEM once per step.
// Warps 0-1 poll 1 flag/lane; warp 0 computes gates + releases.
extern __shared__ float s_dyn[];

__global__ __launch_bounds__(RNN_THREADS, 1) void rnn_kernel(
    const float* __restrict__ whf, const float* __restrict__ whr,
    const float* __restrict__ bhhf, const float* __restrict__ bhhr) {
  float* sWp = s_dyn;                         // 48 rows * 512 (k=512..1023)
  float* sH  = sWp + 48 * 512;                // 2 * H_DIM
  float* sGh = sH + 2 * H_DIM;                // 2 * 48

  int cta = blockIdx.x;
  int d   = cta >> 6;
  int i0  = (cta & 63) * NIDX;
  const float* Wh = d ? whr : whf;
  int tid = threadIdx.x, lane = tid & 31, warp = tid >> 5;

  // register-resident weights: rows r = warp + rr*8, k-chunks 0..3
  ull wreg[6][4][2];
  #pragma unroll
  for (int rr = 0; rr < 6; rr++) {
    int r = warp + rr * 8, g = r >> 4, li = r & 15;
    const float* src = Wh + (size_t)(g * H_DIM + i0 + li) * H_DIM;
    #pragma unroll
    for (int jj = 0; jj < 4; jj++) {
      const ull* p = (const ull*)(src + jj * 128 + lane * 4);
      wreg[rr][jj][0] = p[0];
      wreg[rr][jj][1] = p[1];
    }
  }
  // smem weights: k-chunks 4..7 of all 48 rows
  for (int r = 0; r < 48; r++) {
    int g = r >> 4, li = r & 15;
    const float* src = Wh + (size_t)(g * H_DIM + i0 + li) * H_DIM + 512;
    for (int k = tid; k < 512; k += RNN_THREADS) sWp[r * 512 + k] = src[k];
  }

  bool isGate = tid < 32;               // warp 0: (sentence, idx)
  int gs = tid & 1, gli = tid >> 1;
  float bhn = 0.f, hold = 0.f;
  if (isGate) {
    bhn  = (d ? bhhr : bhhf)[2 * H_DIM + i0 + gli];
    hold = g_h[0][d][gs][i0 + gli];
  }
  unsigned* myflag = g_flag + cta * 32;
  const unsigned* flagbase = g_flag + (d * 64) * 32;

  __syncthreads();

  ull hA01[8], hA23[8], hB01[8], hB23[8];

  for (int t = 0; t < L_SEQ; t++) {
    int cur = t & 1, nxt = cur ^ 1;

    // warps 0-1: poll (1 flag per lane), then stage h(t) into sH (8KB)
    if (warp < 2) {
      int idx = warp * 32 + lane;
      if (t) {
        const unsigned* fp = flagbase + idx * 32;
        unsigned tgt = (unsigned)t;
        while (ld_acq(fp) < tgt) { }
      }
      const float4* src = (const float4*)&g_h[cur][d][0][0];  // 512 float4
      float4* dst = (float4*)sH;
      #pragma unroll
      for (int q = 0; q < 8; q++) dst[idx + q * 64] = ldcg_f4(src + idx + q * 64);
    }
    __syncthreads();   // S1: h staged

    // warp 0: prefetch gx(t) (consumed after S2 — DRAM latency hidden)
    float gxr = 0.f, gxz = 0.f, gxn = 0.f;
    if (isGate) {
      int trow = d ? (L_SEQ - 1 - t) : t;
      const float* gxp = &g_gx[gs * 2 + d][trow][0];
      gxr = __ldg(gxp + i0 + gli);
      gxz = __ldg(gxp + H_DIM + i0 + gli);
      gxn = __ldg(gxp + 2 * H_DIM + i0 + gli);
    }

    // h -> registers
    #pragma unroll
    for (int j = 0; j < 8; j++) {
      ulonglong2 va = *(ulonglong2*)(sH + j * 128 + lane * 4);
      ulonglong2 vb = *(ulonglong2*)(sH + H_DIM + j * 128 + lane * 4);
      hA01[j] = va.x; hA23[j] = va.y;
      hB01[j] = vb.x; hB23[j] = vb.y;
    }

    // dots: 6 rows/warp, both sentences; k 0..511 from regs, 512..1023 from smem
    #pragma unroll
    for (int rr = 0; rr < 6; rr++) {
      int r = warp + rr * 8;
      ull aA0 = 0, aA1 = 0, aB0 = 0, aB1 = 0;
      #pragma unroll
      for (int jj = 0; jj < 4; jj++) {
        ffma2(aA0, wreg[rr][jj][0], hA01[jj]);
        ffma2(aA1, wreg[rr][jj][1], hA23[jj]);
        ffma2(aB0, wreg[rr][jj][0], hB01[jj]);
        ffma2(aB1, wreg[rr][jj][1], hB23[jj]);
      }
      const float* wp = sWp + r * 512 + lane * 4;
      #pragma unroll
      for (int jj = 0; jj < 4; jj++) {
        ulonglong2 w = *(const ulonglong2*)(wp + jj * 128);
        ffma2(aA0, w.x, hA01[4 + jj]);
        ffma2(aA1, w.y, hA23[4 + jj]);
        ffma2(aB0, w.x, hB01[4 + jj]);
        ffma2(aB1, w.y, hB23[4 + jj]);
      }
      float va = pairsum(aA0) + pairsum(aA1);
      float vb = pairsum(aB0) + pairsum(aB1);
      #pragma unroll
      for (int off = 16; off > 0; off >>= 1) {
        va += __shfl_xor_sync(0xffffffffu, va, off);
        vb += __shfl_xor_sync(0xffffffffu, vb, off);
      }
      if (lane == 0) { sGh[r] = va; sGh[48 + r] = vb; }
    }
    __syncthreads();   // S2: sGh ready

    // warp 0: gates + publish; other warps loop back to next poll/stage
    if (warp == 0) {
      float ghr = sGh[gs * 48 + gli];
      float ghz = sGh[gs * 48 + 16 + gli];
      float ghn = sGh[gs * 48 + 32 + gli];
      float r_ = sigm(gxr + ghr);
      float z_ = sigm(gxz + ghz);
      float ag = gxn + r_ * (ghn + bhn);
      ag = fminf(fmaxf(ag, -15.f), 15.f);
      float e = __expf(-2.f * ag);
      float n_ = (1.f - e) / (1.f + e);
      float hnew = (1.f - z_) * n_ + z_ * hold;
      hold = hnew;
      g_h[nxt][d][gs][i0 + gli] = hnew;
      __syncwarp();
      if (lane == 0) st_rel(myflag, (unsigned)(t + 1));
    }
  }
}

// ---------------- head ----------------
__global__ __launch_bounds__(256) void head1(const float* __restrict__ W2,
                                             const float* __restrict__ b2) {
  __shared__ float ht[H_DIM];
  __shared__ float wsum[8];
  int j = blockIdx.x, tid = threadIdx.x, lane = tid & 31, warp = tid >> 5;
  const float* fA = (j < 2) ? &g_h[0][0][0][0] : &g_h[0][1][0][0];
  const float* fB = (j < 2) ? &g_h[0][0][1][0] : &g_h[0][1][1][0];
  for (int k = tid; k < H_DIM; k += 256) {
    float a = fA[k], b = fB[k];
    ht[k] = (j & 1) ? a * b : fabsf(a - b);
  }
  __syncthreads();

  int tbase = blockIdx.y * 64;
  float acc = 0.f;
  for (int t = tbase + warp; t < tbase + 64; t += 8) {
    const float4* w = (const float4*)(W2 + (size_t)t * H_DIM) + lane;
    const float4* h4 = (const float4*)ht + lane;
    float dsum = 0.f;
    #pragma unroll
    for (int q = 0; q < 8; q++) {
      float4 wv = __ldg(w + q * 32);
      float4 hv = h4[q * 32];
      dsum += wv.x * hv.x + wv.y * hv.y + wv.z * hv.z + wv.w * hv.w;
    }
    #pragma unroll
    for (int off = 16; off > 0; off >>= 1)
      dsum += __shfl_xor_sync(0xffffffffu, dsum, off);
    if (lane == 0) acc += fmaxf(dsum + b2[t], 0.f);
  }
  if (lane == 0) wsum[warp] = acc;
  __syncthreads();
  if (tid == 0) {
    float s = 0.f;
    #pragma unroll
    for (int w = 0; w < 8; w++) s += wsum[w];
    atomicAdd(&g_hs[j], s);
  }
}

__global__ void head2(const float* __restrict__ Wl, const float* __restrict__ bl,
                      float* __restrict__ out) {
  float s = bl[0];
  #pragma unroll
  for (int j = 0; j < 4; j++) s += g_hs[j] * Wl[j];
  out[0] = 1.f / (1.f + __expf(-s));
}

// ---------------- launch ----------------
extern "C" void kernel_launch(void* const* d_in, const int* in_sizes, int n_in,
                              void* d_out, int out_size) {
  const int*   sentA  = (const int*)d_in[0];
  const int*   sentB  = (const int*)d_in[1];
  const float* hidden = (const float*)d_in[2];
  const float* emb    = (const float*)d_in[3];
  const float* w_ih_f = (const float*)d_in[4];
  const float* w_hh_f = (const float*)d_in[5];
  const float* b_ih_f = (const float*)d_in[6];
  const float* b_hh_f = (const float*)d_in[7];
  const float* w_ih_r = (const float*)d_in[8];
  const float* w_hh_r = (const float*)d_in[9];
  const float* b_ih_r = (const float*)d_in[10];
  const float* b_hh_r = (const float*)d_in[11];
  const float* W2     = (const float*)d_in[12];
  const float* b2     = (const float*)d_in[13];
  const float* Wl     = (const float*)d_in[14];
  const float* bl     = (const float*)d_in[15];
  float* out = (float*)d_out;

  int rnn_smem = (48 * 512 + 2 * H_DIM + 96) * (int)sizeof(float);
  cudaFuncSetAttribute(rnn_kernel, cudaFuncAttributeMaxDynamicSharedMemorySize, rnn_smem);

  init_kernel<<<32, 256>>>(hidden);

  dim3 ggrid(H3 / 128, L_SEQ / 128, 4);
  gemm_gx<<<ggrid, 256>>>(sentA, sentB, emb, w_ih_f, w_ih_r,
                          b_ih_f, b_hh_f, b_ih_r, b_hh_r);

  rnn_kernel<<<RNN_NCTA, RNN_THREADS, rnn_smem>>>(w_hh_f, w_hh_r, b_hh_f, b_hh_r);

  head1<<<dim3(4, 8), 256>>>(W2, b2);
  head2<<<1, 1>>>(Wl, bl, out);
}